// round 2
// baseline (speedup 1.0000x reference)
#include <cuda_runtime.h>
#include <cuda_bf16.h>

// NCC loss, fully fused, v2: 4 columns/thread, float4 smem traffic.
// Five 9x9 box sums via separable sliding windows:
//   horizontal: 3x LDS.128 per array per row (12 taps), sliding 9-sums
//   vertical:   running add/sub with a 9-row float4 SMEM ring
// then per-pixel cc and a global mean. One pass over the 64 MB of inputs.

#define STRIPW 512           // output columns per CTA
#define BW     128           // threads per CTA (4 cols each)
#define CH     64            // output rows per CTA
#define HALO   4
#define WIN    9
#define BUFW   (STRIPW + 2*HALO)       // 520 staged columns per row
#define RING_F4 (WIN * 5 * BW)         // ring float4 count
#define SMEM_BYTES (RING_F4*16 + 2*2*BUFW*4 + BW*4)   // 92160 + 8320 + 512

__device__ double g_acc;

__global__ void ncc_zero_kernel() { g_acc = 0.0; }

__device__ __forceinline__ float cc_term(float vI, float vJ, float vI2,
                                         float vJ2, float vIJ) {
    const float inv = 1.0f / 81.0f;
    const float uI = vI * inv;
    const float uJ = vJ * inv;
    const float cross = fmaf(-uI, uJ, vIJ * inv);
    const float Ivar  = fmaf(-uI, uI, vI2 * inv);
    const float Jvar  = fmaf(-uJ, uJ, vJ2 * inv);
    return cross * rsqrtf(fmaxf(Ivar * Jvar, 1e-7f));
}

__global__ __launch_bounds__(BW)
void ncc_main_kernel(const float* __restrict__ A,   // y_pred
                     const float* __restrict__ Bt,  // y_true
                     int H, int W)
{
    extern __shared__ unsigned char smem_raw[];
    float4* ring = (float4*)smem_raw;                          // [WIN][5][BW]
    float*  sI   = (float*)(smem_raw + RING_F4 * 16);          // [2][BUFW]
    float*  sJ   = sI + 2 * BUFW;                              // [2][BUFW]
    float*  red  = sJ + 2 * BUFW;                              // [BW]

    const int t  = threadIdx.x;
    const int c0 = blockIdx.x * STRIPW;
    const int r0 = blockIdx.y * CH;
    const size_t base = (size_t)blockIdx.z * (size_t)H * (size_t)W;

    // zero the vertical ring (rows outside the image contribute zero)
    for (int i = t; i < RING_F4; i += BW)
        ring[i] = make_float4(0.f, 0.f, 0.f, 0.f);
    __syncthreads();

    float4 vI  = make_float4(0,0,0,0), vJ  = vI, vI2 = vI, vJ2 = vI, vIJ = vI;
    float acc = 0.f;
    int slot = 0;

    for (int ir = r0 - HALO; ir < r0 + CH + HALO; ++ir) {
        float4 hI  = make_float4(0,0,0,0);
        float4 hJ  = hI, hI2 = hI, hJ2 = hI, hIJ = hI;

        if (ir >= 0 && ir < H) {                 // block-uniform condition
            const int buf = ir & 1;
            const float* __restrict__ rowJ = A  + base + (size_t)ir * W;  // pred
            const float* __restrict__ rowI = Bt + base + (size_t)ir * W;  // true

            // stage row segment [c0-4, c0+STRIPW+4) with zero padding
            float* dI = sI + buf * BUFW;
            float* dJ = sJ + buf * BUFW;
            for (int i = t; i < BUFW; i += BW) {
                const int gc = c0 - HALO + i;
                const bool ok = (gc >= 0) & (gc < W);
                dI[i] = ok ? __ldg(rowI + gc) : 0.0f;
                dJ[i] = ok ? __ldg(rowJ + gc) : 0.0f;
            }
            __syncthreads();   // double-buffered: single barrier per row

            // 12 taps via 3x LDS.128 per array (lane byte offset 16t: conflict-free)
            const float4* pI4 = (const float4*)(sI + buf * BUFW);
            const float4* pJ4 = (const float4*)(sJ + buf * BUFW);
            const float4 IA = pI4[t], IB = pI4[t + 1], IC = pI4[t + 2];
            const float4 JA = pJ4[t], JB = pJ4[t + 1], JC = pJ4[t + 2];

            float ei[12] = {IA.x, IA.y, IA.z, IA.w, IB.x, IB.y, IB.z, IB.w,
                            IC.x, IC.y, IC.z, IC.w};
            float ej[12] = {JA.x, JA.y, JA.z, JA.w, JB.x, JB.y, JB.z, JB.w,
                            JC.x, JC.y, JC.z, JC.w};
            float q2i[12], q2j[12], qij[12];
            #pragma unroll
            for (int k = 0; k < 12; ++k) {
                q2i[k] = ei[k] * ei[k];
                q2j[k] = ej[k] * ej[k];
                qij[k] = ei[k] * ej[k];
            }

            // sliding horizontal 9-sums for the 4 owned columns
            float a = 0, b = 0, c2 = 0, d = 0, e = 0;
            #pragma unroll
            for (int k = 0; k < WIN; ++k) {
                a += ei[k];  b += ej[k];  c2 += q2i[k];  d += q2j[k];  e += qij[k];
            }
            hI.x  = a;  hJ.x  = b;  hI2.x = c2;  hJ2.x = d;  hIJ.x = e;
            hI.y  = a  - ei[0]  + ei[9];
            hJ.y  = b  - ej[0]  + ej[9];
            hI2.y = c2 - q2i[0] + q2i[9];
            hJ2.y = d  - q2j[0] + q2j[9];
            hIJ.y = e  - qij[0] + qij[9];
            hI.z  = hI.y  - ei[1]  + ei[10];
            hJ.z  = hJ.y  - ej[1]  + ej[10];
            hI2.z = hI2.y - q2i[1] + q2i[10];
            hJ2.z = hJ2.y - q2j[1] + q2j[10];
            hIJ.z = hIJ.y - qij[1] + qij[10];
            hI.w  = hI.z  - ei[2]  + ei[11];
            hJ.w  = hJ.z  - ej[2]  + ej[11];
            hI2.w = hI2.z - q2i[2] + q2i[11];
            hJ2.w = hJ2.z - q2j[2] + q2j[11];
            hIJ.w = hIJ.z - qij[2] + qij[11];
        }

        // vertical running window (float4 ring, lane-contiguous: conflict-free)
        {
            float4* r;
            float4 old;
            r = &ring[(slot * 5 + 0) * BW + t]; old = *r; *r = hI;
            vI.x  += hI.x  - old.x; vI.y  += hI.y  - old.y;
            vI.z  += hI.z  - old.z; vI.w  += hI.w  - old.w;
            r = &ring[(slot * 5 + 1) * BW + t]; old = *r; *r = hJ;
            vJ.x  += hJ.x  - old.x; vJ.y  += hJ.y  - old.y;
            vJ.z  += hJ.z  - old.z; vJ.w  += hJ.w  - old.w;
            r = &ring[(slot * 5 + 2) * BW + t]; old = *r; *r = hI2;
            vI2.x += hI2.x - old.x; vI2.y += hI2.y - old.y;
            vI2.z += hI2.z - old.z; vI2.w += hI2.w - old.w;
            r = &ring[(slot * 5 + 3) * BW + t]; old = *r; *r = hJ2;
            vJ2.x += hJ2.x - old.x; vJ2.y += hJ2.y - old.y;
            vJ2.z += hJ2.z - old.z; vJ2.w += hJ2.w - old.w;
            r = &ring[(slot * 5 + 4) * BW + t]; old = *r; *r = hIJ;
            vIJ.x += hIJ.x - old.x; vIJ.y += hIJ.y - old.y;
            vIJ.z += hIJ.z - old.z; vIJ.w += hIJ.w - old.w;
        }
        if (++slot == WIN) slot = 0;

        // output row ir-4 is complete once 9 rows are in the window
        if (ir >= r0 + HALO) {
            acc += cc_term(vI.x, vJ.x, vI2.x, vJ2.x, vIJ.x);
            acc += cc_term(vI.y, vJ.y, vI2.y, vJ2.y, vIJ.y);
            acc += cc_term(vI.z, vJ.z, vI2.z, vJ2.z, vIJ.z);
            acc += cc_term(vI.w, vJ.w, vI2.w, vJ2.w, vIJ.w);
        }
    }

    // block reduction -> one double atomic per CTA
    red[t] = acc;
    __syncthreads();
    #pragma unroll
    for (int s = BW / 2; s > 0; s >>= 1) {
        if (t < s) red[t] += red[t + s];
        __syncthreads();
    }
    if (t == 0) atomicAdd(&g_acc, (double)red[0]);
}

__global__ void ncc_finalize_kernel(float* out, double count)
{
    out[0] = (float)(1.0 - g_acc / count);
}

extern "C" void kernel_launch(void* const* d_in, const int* in_sizes, int n_in,
                              void* d_out, int out_size)
{
    const float* y_pred = (const float*)d_in[0];
    const float* y_true = (const float*)d_in[1];
    float* out = (float*)d_out;

    const int H = 1024, W = 1024;
    const long long n = (long long)in_sizes[0];
    const int B = (int)(n / ((long long)H * W));   // 8

    // dynamic smem (101 KB > 48 KB static limit); attribute set is idempotent
    // and not a stream operation, so it is graph-capture-safe.
    cudaFuncSetAttribute(ncc_main_kernel,
                         cudaFuncAttributeMaxDynamicSharedMemorySize, SMEM_BYTES);

    ncc_zero_kernel<<<1, 1>>>();

    dim3 grid(W / STRIPW, H / CH, B);   // (2, 16, 8) = 256 CTAs
    ncc_main_kernel<<<grid, BW, SMEM_BYTES>>>(y_pred, y_true, H, W);

    const double count = (double)B * (double)H * (double)W;
    ncc_finalize_kernel<<<1, 1>>>(out, count);
}

// round 4
// speedup vs baseline: 2.3970x; 2.3970x over previous
#include <cuda_runtime.h>
#include <cuda_bf16.h>

// NCC loss, fully fused, v4: barrier-free main loop + software-pipelined row
// loads (prefetch row ir+1 while computing row ir).
//  - taps: 3 predicated LDG.128 per array per row, straight from gmem (the
//    overlapping 512B windows hit L1); no staging smem, no __syncthreads.
//  - vertical: running add/sub with a 9-row float4 smem ring, thread-private
//    columns (no sync needed).
//  - per-CTA partial sums to a device array slot; tiny finalize kernel.

#define BW     128           // threads per CTA; 4 columns each
#define STRIPW 512           // output columns per CTA
#define CH     64            // output rows per CTA
#define HALO   4
#define WIN    9
#define RING_F4 (WIN * 5 * BW)
#define SMEM_BYTES (RING_F4 * 16 + BW * 4)
#define NBLK   256           // (1024/STRIPW) * (1024/CH) * 8

__device__ float g_part[NBLK];   // per-CTA partials (fully rewritten each launch)

__device__ __forceinline__ float cc_term(float vI, float vJ, float vI2,
                                         float vJ2, float vIJ) {
    const float inv = 1.0f / 81.0f;
    const float uI = vI * inv;
    const float uJ = vJ * inv;
    const float cross = fmaf(-uI, uJ, vIJ * inv);
    const float Ivar  = fmaf(-uI, uI, vI2 * inv);
    const float Jvar  = fmaf(-uJ, uJ, vJ2 * inv);
    return cross * rsqrtf(fmaxf(Ivar * Jvar, 1e-7f));
}

__global__ __launch_bounds__(BW, 2)
void ncc_main_kernel(const float* __restrict__ A,   // y_pred
                     const float* __restrict__ Bt,  // y_true
                     int H, int W)
{
    extern __shared__ unsigned char smem_raw[];
    float4* ring = (float4*)smem_raw;                        // [WIN][5][BW]
    float*  red  = (float*)(smem_raw + RING_F4 * 16);        // [BW]

    const int t  = threadIdx.x;
    const int c  = blockIdx.x * STRIPW + 4 * t;   // first owned column
    const int r0 = blockIdx.y * CH;
    const size_t base = (size_t)blockIdx.z * (size_t)H * (size_t)W;

    const bool okL = (c >= 4);          // left tap block in range?
    const bool okR = (c + 7 < W);       // right tap block in range?
    const int  i0  = c >> 2;            // float4 index of owned block
    const float4 z4 = make_float4(0.f, 0.f, 0.f, 0.f);

    // zero my private ring slots (no sync needed: columns are thread-private)
    #pragma unroll
    for (int s = 0; s < WIN; ++s)
        #pragma unroll
        for (int q = 0; q < 5; ++q)
            ring[(s * 5 + q) * BW + t] = z4;

    float4 vI  = z4, vJ = z4, vI2 = z4, vJ2 = z4, vIJ = z4;
    float acc = 0.f;
    int slot = 0;

    // --- software pipeline: L* holds row `ir`, N* holds row `ir+1` ---
    float4 LIA, LIB, LIC, LJA, LJB, LJC;
    float4 NIA, NIB, NIC, NJA, NJB, NJC;

    // prime the pipeline with the first row (ir = r0 - HALO)
    {
        const int ir = r0 - HALO;
        if (ir >= 0 && ir < H) {
            const float4* __restrict__ rJ = (const float4*)(A  + base + (size_t)ir * W);
            const float4* __restrict__ rI = (const float4*)(Bt + base + (size_t)ir * W);
            LIA = okL ? __ldg(rI + i0 - 1) : z4;
            LIB = __ldg(rI + i0);
            LIC = okR ? __ldg(rI + i0 + 1) : z4;
            LJA = okL ? __ldg(rJ + i0 - 1) : z4;
            LJB = __ldg(rJ + i0);
            LJC = okR ? __ldg(rJ + i0 + 1) : z4;
        } else {
            LIA = LIB = LIC = LJA = LJB = LJC = z4;
        }
    }

    #pragma unroll 1
    for (int ir = r0 - HALO; ir < r0 + CH + HALO; ++ir) {
        // ---- prefetch row ir+1 (issued before any use of L*) ----
        {
            const int nr = ir + 1;
            if (nr >= 0 && nr < H && nr < r0 + CH + HALO) {
                const float4* __restrict__ rJ = (const float4*)(A  + base + (size_t)nr * W);
                const float4* __restrict__ rI = (const float4*)(Bt + base + (size_t)nr * W);
                NIA = okL ? __ldg(rI + i0 - 1) : z4;
                NIB = __ldg(rI + i0);
                NIC = okR ? __ldg(rI + i0 + 1) : z4;
                NJA = okL ? __ldg(rJ + i0 - 1) : z4;
                NJB = __ldg(rJ + i0);
                NJC = okR ? __ldg(rJ + i0 + 1) : z4;
            } else {
                NIA = NIB = NIC = NJA = NJB = NJC = z4;
            }
        }

        // ---- compute with row ir (registers L*) ----
        float4 hI = z4, hJ = z4, hI2 = z4, hJ2 = z4, hIJ = z4;
        if (ir >= 0 && ir < H) {                 // block-uniform condition
            const float ei[12] = {LIA.x, LIA.y, LIA.z, LIA.w, LIB.x, LIB.y,
                                  LIB.z, LIB.w, LIC.x, LIC.y, LIC.z, LIC.w};
            const float ej[12] = {LJA.x, LJA.y, LJA.z, LJA.w, LJB.x, LJB.y,
                                  LJB.z, LJB.w, LJC.x, LJC.y, LJC.z, LJC.w};
            float q2i[12], q2j[12], qij[12];
            #pragma unroll
            for (int k = 0; k < 12; ++k) {
                q2i[k] = ei[k] * ei[k];
                q2j[k] = ej[k] * ej[k];
                qij[k] = ei[k] * ej[k];
            }

            // sliding horizontal 9-sums for the 4 owned columns
            float a = 0, b = 0, c2 = 0, d = 0, e = 0;
            #pragma unroll
            for (int k = 0; k < WIN; ++k) {
                a += ei[k]; b += ej[k]; c2 += q2i[k]; d += q2j[k]; e += qij[k];
            }
            hI.x  = a;  hJ.x  = b;  hI2.x = c2;  hJ2.x = d;  hIJ.x = e;
            hI.y  = a  - ei[0]  + ei[9];
            hJ.y  = b  - ej[0]  + ej[9];
            hI2.y = c2 - q2i[0] + q2i[9];
            hJ2.y = d  - q2j[0] + q2j[9];
            hIJ.y = e  - qij[0] + qij[9];
            hI.z  = hI.y  - ei[1]  + ei[10];
            hJ.z  = hJ.y  - ej[1]  + ej[10];
            hI2.z = hI2.y - q2i[1] + q2i[10];
            hJ2.z = hJ2.y - q2j[1] + q2j[10];
            hIJ.z = hIJ.y - qij[1] + qij[10];
            hI.w  = hI.z  - ei[2]  + ei[11];
            hJ.w  = hJ.z  - ej[2]  + ej[11];
            hI2.w = hI2.z - q2i[2] + q2i[11];
            hJ2.w = hJ2.z - q2j[2] + q2j[11];
            hIJ.w = hIJ.z - qij[2] + qij[11];
        }

        // vertical running window (thread-private float4 ring, no sync)
        {
            float4* r; float4 old;
            r = &ring[(slot * 5 + 0) * BW + t]; old = *r; *r = hI;
            vI.x  += hI.x  - old.x; vI.y  += hI.y  - old.y;
            vI.z  += hI.z  - old.z; vI.w  += hI.w  - old.w;
            r = &ring[(slot * 5 + 1) * BW + t]; old = *r; *r = hJ;
            vJ.x  += hJ.x  - old.x; vJ.y  += hJ.y  - old.y;
            vJ.z  += hJ.z  - old.z; vJ.w  += hJ.w  - old.w;
            r = &ring[(slot * 5 + 2) * BW + t]; old = *r; *r = hI2;
            vI2.x += hI2.x - old.x; vI2.y += hI2.y - old.y;
            vI2.z += hI2.z - old.z; vI2.w += hI2.w - old.w;
            r = &ring[(slot * 5 + 3) * BW + t]; old = *r; *r = hJ2;
            vJ2.x += hJ2.x - old.x; vJ2.y += hJ2.y - old.y;
            vJ2.z += hJ2.z - old.z; vJ2.w += hJ2.w - old.w;
            r = &ring[(slot * 5 + 4) * BW + t]; old = *r; *r = hIJ;
            vIJ.x += hIJ.x - old.x; vIJ.y += hIJ.y - old.y;
            vIJ.z += hIJ.z - old.z; vIJ.w += hIJ.w - old.w;
        }
        if (++slot == WIN) slot = 0;

        // output row ir-4 is complete once 9 rows are in the window
        if (ir >= r0 + HALO) {
            acc += cc_term(vI.x, vJ.x, vI2.x, vJ2.x, vIJ.x);
            acc += cc_term(vI.y, vJ.y, vI2.y, vJ2.y, vIJ.y);
            acc += cc_term(vI.z, vJ.z, vI2.z, vJ2.z, vIJ.z);
            acc += cc_term(vI.w, vJ.w, vI2.w, vJ2.w, vIJ.w);
        }

        // rotate pipeline registers
        LIA = NIA; LIB = NIB; LIC = NIC;
        LJA = NJA; LJB = NJB; LJC = NJC;
    }

    // block reduction -> one partial-sum slot per CTA (plain store, no atomic)
    red[t] = acc;
    __syncthreads();
    #pragma unroll
    for (int s = BW / 2; s > 0; s >>= 1) {
        if (t < s) red[t] += red[t + s];
        __syncthreads();
    }
    if (t == 0) {
        const int bid = blockIdx.x +
                        gridDim.x * (blockIdx.y + gridDim.y * blockIdx.z);
        g_part[bid] = red[0];
    }
}

__global__ __launch_bounds__(NBLK)
void ncc_finalize_kernel(float* out, double count)
{
    __shared__ double sred[NBLK];
    const int t = threadIdx.x;
    sred[t] = (double)g_part[t];
    __syncthreads();
    #pragma unroll
    for (int s = NBLK / 2; s > 0; s >>= 1) {
        if (t < s) sred[t] += sred[t + s];
        __syncthreads();
    }
    if (t == 0) out[0] = (float)(1.0 - sred[0] / count);
}

extern "C" void kernel_launch(void* const* d_in, const int* in_sizes, int n_in,
                              void* d_out, int out_size)
{
    const float* y_pred = (const float*)d_in[0];
    const float* y_true = (const float*)d_in[1];
    float* out = (float*)d_out;

    const int H = 1024, W = 1024;
    const long long n = (long long)in_sizes[0];
    const int B = (int)(n / ((long long)H * W));   // 8

    // dynamic smem > 48 KB; attribute set is idempotent and capture-safe.
    cudaFuncSetAttribute(ncc_main_kernel,
                         cudaFuncAttributeMaxDynamicSharedMemorySize, SMEM_BYTES);

    dim3 grid(W / STRIPW, H / CH, B);   // (2, 16, 8) = 256 CTAs
    ncc_main_kernel<<<grid, BW, SMEM_BYTES>>>(y_pred, y_true, H, W);

    const double count = (double)B * (double)H * (double)W;
    ncc_finalize_kernel<<<1, NBLK>>>(out, count);
}

// round 6
// speedup vs baseline: 3.2798x; 1.3683x over previous
#include <cuda_runtime.h>
#include <cuda_bf16.h>

// NCC loss, fully fused, v5 (resubmit — previous round never ran):
// packed f32x2 math + fused finalize.
//  - taps: 3 predicated LDG.128 per array per row, pipelined (prefetch row+1).
//  - channels packed as f32x2: (I,J) and (I2,J2) share one 64-bit register
//    through products, horizontal sliding 9-sums, vertical ring, cc math.
//  - vertical: running add/sub with a 9-row ulonglong2 smem ring,
//    thread-private columns (no sync needed), LDS.128/STS.128.
//  - finalize fused via last-CTA pattern (no second launch, no zero kernel).

#define BW     128           // threads per CTA; 4 columns each
#define STRIPW 512           // output columns per CTA
#define CH     64            // output rows per CTA
#define HALO   4
#define WIN    9
#define NBLK   256           // (1024/STRIPW) * (1024/CH) * 8

// ring: 5 ulonglong2 slots per window row, each slot = BW entries
#define RING_U2    (WIN * 5 * BW)          // total ulonglong2 entries
#define SMEM_BYTES (RING_U2 * 16 + BW * 8) // ring + double reduction buffer

typedef unsigned long long ull;

__device__ float        g_part[NBLK];  // per-CTA partials (rewritten each launch)
__device__ unsigned int g_count;       // zero at load; reset to 0 by last CTA

// ---- f32x2 packed helpers (Blackwell PTX) ----
__device__ __forceinline__ ull pk(float lo, float hi) {
    ull r; asm("mov.b64 %0,{%1,%2};" : "=l"(r) : "f"(lo), "f"(hi)); return r;
}
__device__ __forceinline__ void upk(ull v, float& lo, float& hi) {
    asm("mov.b64 {%0,%1},%2;" : "=f"(lo), "=f"(hi) : "l"(v));
}
__device__ __forceinline__ ull m2(ull a, ull b) {
    ull r; asm("mul.rn.f32x2 %0,%1,%2;" : "=l"(r) : "l"(a), "l"(b)); return r;
}
__device__ __forceinline__ ull a2(ull a, ull b) {
    ull r; asm("add.rn.f32x2 %0,%1,%2;" : "=l"(r) : "l"(a), "l"(b)); return r;
}
__device__ __forceinline__ ull f2(ull a, ull b, ull c) {  // a*b+c
    ull r; asm("fma.rn.f32x2 %0,%1,%2,%3;" : "=l"(r) : "l"(a), "l"(b), "l"(c));
    return r;
}

__global__ __launch_bounds__(BW, 2)
void ncc_main_kernel(const float* __restrict__ A,   // y_pred
                     const float* __restrict__ Bt,  // y_true
                     float* __restrict__ out,
                     int H, int W)
{
    extern __shared__ unsigned char smem_raw[];
    ulonglong2* ring = (ulonglong2*)smem_raw;               // [WIN][5][BW]
    double*     dred = (double*)(smem_raw + RING_U2 * 16);  // [BW]

    const int t  = threadIdx.x;
    const int c  = blockIdx.x * STRIPW + 4 * t;   // first owned column
    const int r0 = blockIdx.y * CH;
    const size_t base = (size_t)blockIdx.z * (size_t)H * (size_t)W;

    const bool okL = (c >= 4);
    const bool okR = (c + 7 < W);
    const int  i0  = c >> 2;
    const float4 z4 = make_float4(0.f, 0.f, 0.f, 0.f);
    const ull   Z2   = 0ULL;
    const ull   NEG1 = pk(-1.0f, -1.0f);
    const float inv  = 1.0f / 81.0f;
    const ull   INV2 = pk(inv, inv);

    // zero my private ring slots (thread-private columns: no sync needed)
    #pragma unroll
    for (int s = 0; s < WIN * 5; ++s)
        ring[s * BW + t] = make_ulonglong2(0ULL, 0ULL);

    // packed accumulators: vIJ[c]=(vI,vJ), vSq[c]=(vI2,vJ2) per col; vP pairs
    ull vIJ0 = Z2, vIJ1 = Z2, vIJ2 = Z2, vIJ3 = Z2;
    ull vSq0 = Z2, vSq1 = Z2, vSq2 = Z2, vSq3 = Z2;
    ull vP01 = Z2, vP23 = Z2;
    float acc = 0.f;
    int slot = 0;

    // --- software pipeline: L* holds row `ir`, N* holds row `ir+1` ---
    float4 LIA, LIB, LIC, LJA, LJB, LJC;
    float4 NIA, NIB, NIC, NJA, NJB, NJC;
    {
        const int ir = r0 - HALO;
        if (ir >= 0 && ir < H) {
            const float4* __restrict__ rJ = (const float4*)(A  + base + (size_t)ir * W);
            const float4* __restrict__ rI = (const float4*)(Bt + base + (size_t)ir * W);
            LIA = okL ? __ldg(rI + i0 - 1) : z4;
            LIB = __ldg(rI + i0);
            LIC = okR ? __ldg(rI + i0 + 1) : z4;
            LJA = okL ? __ldg(rJ + i0 - 1) : z4;
            LJB = __ldg(rJ + i0);
            LJC = okR ? __ldg(rJ + i0 + 1) : z4;
        } else {
            LIA = LIB = LIC = LJA = LJB = LJC = z4;
        }
    }

    #pragma unroll 1
    for (int ir = r0 - HALO; ir < r0 + CH + HALO; ++ir) {
        // ---- prefetch row ir+1 (issued before any use of L*) ----
        {
            const int nr = ir + 1;
            if (nr >= 0 && nr < H && nr < r0 + CH + HALO) {
                const float4* __restrict__ rJ = (const float4*)(A  + base + (size_t)nr * W);
                const float4* __restrict__ rI = (const float4*)(Bt + base + (size_t)nr * W);
                NIA = okL ? __ldg(rI + i0 - 1) : z4;
                NIB = __ldg(rI + i0);
                NIC = okR ? __ldg(rI + i0 + 1) : z4;
                NJA = okL ? __ldg(rJ + i0 - 1) : z4;
                NJB = __ldg(rJ + i0);
                NJC = okR ? __ldg(rJ + i0 + 1) : z4;
            } else {
                NIA = NIB = NIC = NJA = NJB = NJC = z4;
            }
        }

        // ---- compute with row ir ----
        ull hIJ0 = Z2, hIJ1 = Z2, hIJ2 = Z2, hIJ3 = Z2;
        ull hSq0 = Z2, hSq1 = Z2, hSq2 = Z2, hSq3 = Z2;
        ull hP01 = Z2, hP23 = Z2;

        if (ir >= 0 && ir < H) {                 // block-uniform condition
            const float ei[12] = {LIA.x, LIA.y, LIA.z, LIA.w, LIB.x, LIB.y,
                                  LIB.z, LIB.w, LIC.x, LIC.y, LIC.z, LIC.w};
            const float ej[12] = {LJA.x, LJA.y, LJA.z, LJA.w, LJB.x, LJB.y,
                                  LJB.z, LJB.w, LJC.x, LJC.y, LJC.z, LJC.w};

            ull pIJ[12], pSq[12];
            float pr[12];
            #pragma unroll
            for (int k = 0; k < 12; ++k) {
                pIJ[k] = pk(ei[k], ej[k]);       // alu-pipe pack
                pSq[k] = m2(pIJ[k], pIJ[k]);     // (ei^2, ej^2) packed
                pr[k]  = ei[k] * ej[k];          // scalar product channel
            }

            // packed horizontal 9-sums + sliding for the 4 owned columns
            ull s = pIJ[0];
            #pragma unroll
            for (int k = 1; k < WIN; ++k) s = a2(s, pIJ[k]);
            hIJ0 = s;
            hIJ1 = a2(f2(pIJ[0], NEG1, hIJ0), pIJ[9]);
            hIJ2 = a2(f2(pIJ[1], NEG1, hIJ1), pIJ[10]);
            hIJ3 = a2(f2(pIJ[2], NEG1, hIJ2), pIJ[11]);

            s = pSq[0];
            #pragma unroll
            for (int k = 1; k < WIN; ++k) s = a2(s, pSq[k]);
            hSq0 = s;
            hSq1 = a2(f2(pSq[0], NEG1, hSq0), pSq[9]);
            hSq2 = a2(f2(pSq[1], NEG1, hSq1), pSq[10]);
            hSq3 = a2(f2(pSq[2], NEG1, hSq2), pSq[11]);

            float sp = pr[0];
            #pragma unroll
            for (int k = 1; k < WIN; ++k) sp += pr[k];
            const float hp0 = sp;
            const float hp1 = hp0 - pr[0] + pr[9];
            const float hp2 = hp1 - pr[1] + pr[10];
            const float hp3 = hp2 - pr[2] + pr[11];
            hP01 = pk(hp0, hp1);
            hP23 = pk(hp2, hp3);
        }

        // ---- vertical running window (thread-private ring, no sync) ----
        {
            ulonglong2* q; ulonglong2 o;
            q = ring + (slot * 5 + 0) * BW + t; o = *q;
            *q = make_ulonglong2(hIJ0, hIJ1);
            vIJ0 = a2(vIJ0, f2(o.x, NEG1, hIJ0));
            vIJ1 = a2(vIJ1, f2(o.y, NEG1, hIJ1));
            q = ring + (slot * 5 + 1) * BW + t; o = *q;
            *q = make_ulonglong2(hIJ2, hIJ3);
            vIJ2 = a2(vIJ2, f2(o.x, NEG1, hIJ2));
            vIJ3 = a2(vIJ3, f2(o.y, NEG1, hIJ3));
            q = ring + (slot * 5 + 2) * BW + t; o = *q;
            *q = make_ulonglong2(hSq0, hSq1);
            vSq0 = a2(vSq0, f2(o.x, NEG1, hSq0));
            vSq1 = a2(vSq1, f2(o.y, NEG1, hSq1));
            q = ring + (slot * 5 + 3) * BW + t; o = *q;
            *q = make_ulonglong2(hSq2, hSq3);
            vSq2 = a2(vSq2, f2(o.x, NEG1, hSq2));
            vSq3 = a2(vSq3, f2(o.y, NEG1, hSq3));
            q = ring + (slot * 5 + 4) * BW + t; o = *q;
            *q = make_ulonglong2(hP01, hP23);
            vP01 = a2(vP01, f2(o.x, NEG1, hP01));
            vP23 = a2(vP23, f2(o.y, NEG1, hP23));
        }
        if (++slot == WIN) slot = 0;

        // ---- cc for completed output row (ir-4) ----
        if (ir >= r0 + HALO) {
            float p0, p1, p2, p3;
            upk(vP01, p0, p1);
            upk(vP23, p2, p3);
            ull vIJs[4] = {vIJ0, vIJ1, vIJ2, vIJ3};
            ull vSqs[4] = {vSq0, vSq1, vSq2, vSq3};
            float ps[4] = {p0, p1, p2, p3};
            #pragma unroll
            for (int cc = 0; cc < 4; ++cc) {
                const ull u   = m2(vIJs[cc], INV2);        // (uI, uJ)
                const ull tv  = m2(vSqs[cc], INV2);        // (I2/81, J2/81)
                const ull uu  = m2(u, u);
                const ull var = a2(tv, m2(uu, NEG1));      // (Ivar, Jvar)
                float uI, uJ, Iv, Jv;
                upk(u, uI, uJ);
                upk(var, Iv, Jv);
                const float muIJ = uI * uJ;
                const float cross = fmaf(ps[cc], inv, -muIJ);
                const float den = fmaxf(Iv * Jv, 1e-7f);
                acc = fmaf(cross, rsqrtf(den), acc);
            }
        }

        // rotate pipeline registers
        LIA = NIA; LIB = NIB; LIC = NIC;
        LJA = NJA; LJB = NJB; LJC = NJC;
    }

    // ---- block reduction -> per-CTA partial ----
    dred[t] = (double)acc;
    __syncthreads();
    #pragma unroll
    for (int s = BW / 2; s > 0; s >>= 1) {
        if (t < s) dred[t] += dred[t + s];
        __syncthreads();
    }

    __shared__ bool amLast;
    if (t == 0) {
        const int bid = blockIdx.x +
                        gridDim.x * (blockIdx.y + gridDim.y * blockIdx.z);
        g_part[bid] = (float)dred[0];
        __threadfence();
        amLast = (atomicAdd(&g_count, 1u) == NBLK - 1u);
    }
    __syncthreads();

    // ---- fused finalize: last CTA reduces all partials ----
    if (amLast) {
        __threadfence();
        float a0, a1;
        asm volatile("ld.global.cg.f32 %0, [%1];" : "=f"(a0) : "l"(g_part + t));
        asm volatile("ld.global.cg.f32 %0, [%1];" : "=f"(a1) : "l"(g_part + t + BW));
        dred[t] = (double)a0 + (double)a1;
        __syncthreads();
        #pragma unroll
        for (int s = BW / 2; s > 0; s >>= 1) {
            if (t < s) dred[t] += dred[t + s];
            __syncthreads();
        }
        if (t == 0) {
            const double count = 8.0 * 1024.0 * 1024.0;
            out[0] = (float)(1.0 - dred[0] / count);
            g_count = 0;   // reset for the next (graph-replayed) launch
        }
    }
}

extern "C" void kernel_launch(void* const* d_in, const int* in_sizes, int n_in,
                              void* d_out, int out_size)
{
    const float* y_pred = (const float*)d_in[0];
    const float* y_true = (const float*)d_in[1];
    float* out = (float*)d_out;

    const int H = 1024, W = 1024;
    const long long n = (long long)in_sizes[0];
    const int B = (int)(n / ((long long)H * W));   // 8

    // dynamic smem > 48 KB; attribute set is idempotent and capture-safe.
    cudaFuncSetAttribute(ncc_main_kernel,
                         cudaFuncAttributeMaxDynamicSharedMemorySize, SMEM_BYTES);

    dim3 grid(W / STRIPW, H / CH, B);   // (2, 16, 8) = 256 CTAs
    ncc_main_kernel<<<grid, BW, SMEM_BYTES>>>(y_pred, y_true, out, H, W);
}